// round 14
// baseline (speedup 1.0000x reference)
#include <cuda_runtime.h>
#include <cuda_bf16.h>
#include <stdint.h>

#define NCELL 81
#define TPB   384

// bf16 A tiles: row stride 136 halves (272 B), 16B-aligned, ldmatrix conflict-free
#define ASTR  136
// ---- float-index smem layout (26884 floats = 107536 B -> 2 CTAs/SM) ----
#define AHI_F 0        // A_hi 96 x 136 halves (6528 f)
#define ALO_F 6528
#define SH_F  13056    // Y2 fp32 81 x 130 (10530 f, +2 pad)
#define SH_STR 130
#define SW1_F 23588    // W1 10x128 (1280)
#define SX_F  24868    // x 81x10 (816)
#define SZ_F  25684    // A_hat@x 81x10 (816)
#define SP_F  26500    // pooled (128)
#define SB_F  26628    // b1|b2 (256)
#define SM_FLOATS 26884
// scratch overlapping the (temporally dead) A region:
#define TRIP_F  0      // phase 1 trips (540 f)
#define RT_F    0      // phase 4 rowtrip 27x128 = 3456
#define CT_F    3456   // phase 4 coltrip 27x128 = 3456
#define POOLP_F 6912   // pool partials 3 x 128 = 384
#define HEADP_F 7296   // head partials 208

// ---- prepacked W2 (bf16 hi/lo) in device-global, B-fragment quad order ----
// layout: [n][g][q][4] halves, quad q holds k = 16g + {2q, 2q+1, 2q+8, 2q+9}
__device__ __align__(16) uint16_t gBhi[128 * 128];
__device__ __align__(16) uint16_t gBlo[128 * 128];

__global__ void prep_w2_kernel(const float* __restrict__ W2) {
    int idx = blockIdx.x * blockDim.x + threadIdx.x;   // 4096 quads
    if (idx >= 4096) return;
    int n = idx >> 5, g = (idx >> 2) & 7, q = idx & 3;
    int kb = 16 * g + 2 * q;
    int ks[4] = { kb, kb + 1, kb + 8, kb + 9 };
    uint16_t h[4], l[4];
    #pragma unroll
    for (int e = 0; e < 4; e++) {
        float w = W2[ks[e] * 128 + n];
        __nv_bfloat16 hb = __float2bfloat16(w);
        float fh = __bfloat162float(hb);
        __nv_bfloat16 lb = __float2bfloat16(w - fh);
        h[e] = __bfloat16_as_ushort(hb);
        l[e] = __bfloat16_as_ushort(lb);
    }
    int off = n * 128 + g * 16 + q * 4;
    uint64_t hv, lv;
    memcpy(&hv, h, 8);
    memcpy(&lv, l, 8);
    *(uint64_t*)(gBhi + off) = hv;
    *(uint64_t*)(gBlo + off) = lv;
}

// ================= constexpr index tables (phase 1) =========================
struct U54 { unsigned v[54]; };
struct U81 { unsigned v[81]; };

static constexpr U54 mkA() {
    U54 r{};
    for (int t = 0; t < 54; t++) {
        int c0 = 0, c1 = 0, c2 = 0;
        if (t < 27) { int i = t / 3, bj = t % 3, base = i * 9 + bj * 3;
                      c0 = base; c1 = base + 1; c2 = base + 2; }
        else        { int u = t - 27, j = u / 3, bi = u % 3, base = bi * 27 + j;
                      c0 = base; c1 = base + 9; c2 = base + 18; }
        r.v[t] = (unsigned)(c0 | (c1 << 8) | (c2 << 16));
    }
    return r;
}
// cell -> i | j<<4 | bi<<8 | bj<<12
static constexpr U81 mkD() {
    U81 r{};
    for (int cell = 0; cell < 81; cell++) {
        int i = cell / 9, j = cell % 9, bi = i / 3, bj = j / 3;
        r.v[cell] = (unsigned)(i | (j << 4) | (bi << 8) | (bj << 12));
    }
    return r;
}
__constant__ U54 cTabA = mkA();
__constant__ U81 cTabD = mkD();

// ================= PTX helpers ==============================================
__device__ __forceinline__ uint32_t smem_to_u32(const void* p) {
    uint32_t a;
    asm("{ .reg .u64 t; cvta.to.shared.u64 t, %1; cvt.u32.u64 %0, t; }"
        : "=r"(a) : "l"(p));
    return a;
}
__device__ __forceinline__ uint32_t cvt2bf16(float v0, float v1) {
    uint32_t r;
    asm("cvt.rn.bf16x2.f32 %0, %1, %2;" : "=r"(r) : "f"(v1), "f"(v0));
    return r;
}
__device__ __forceinline__ void ldsm4(uint32_t& r0, uint32_t& r1,
                                      uint32_t& r2, uint32_t& r3, uint32_t addr) {
    asm volatile("ldmatrix.sync.aligned.m8n8.x4.shared.b16 {%0,%1,%2,%3}, [%4];"
                 : "=r"(r0), "=r"(r1), "=r"(r2), "=r"(r3) : "r"(addr));
}
__device__ __forceinline__ void mma16816(float* c, uint32_t a0, uint32_t a1,
                                         uint32_t a2, uint32_t a3,
                                         uint32_t b0, uint32_t b1) {
    asm volatile(
        "mma.sync.aligned.m16n8k16.row.col.f32.bf16.bf16.f32 "
        "{%0,%1,%2,%3}, {%4,%5,%6,%7}, {%8,%9}, {%0,%1,%2,%3};"
        : "+f"(c[0]), "+f"(c[1]), "+f"(c[2]), "+f"(c[3])
        : "r"(a0), "r"(a1), "r"(a2), "r"(a3), "r"(b0), "r"(b1));
}

// ================= main kernel ==============================================
__global__ __launch_bounds__(TPB, 2)
void sudoku_gnn_kernel(const float* __restrict__ x,
                       const float* __restrict__ W1, const float* __restrict__ b1,
                       const float* __restrict__ b2,
                       const float* __restrict__ Wa, const float* __restrict__ ba,
                       const float* __restrict__ Wc, const float* __restrict__ bc,
                       const float* __restrict__ Wn, const float* __restrict__ bn,
                       const float* __restrict__ Wt, const float* __restrict__ bt,
                       float* __restrict__ out)
{
    extern __shared__ float sm[];
    char*  smb = (char*)sm;
    float* sH  = sm + SH_F;
    float* sW1 = sm + SW1_F;
    float* sX  = sm + SX_F;
    float* sZ  = sm + SZ_F;
    float* sP  = sm + SP_F;
    float* sB  = sm + SB_F;
    float* sTripF = sm + TRIP_F;
    float* sPoolP = sm + POOLP_F;
    float* sHeadP = sm + HEADP_F;

    const int tid  = threadIdx.x;
    const int wid  = tid >> 5;
    const int lane = tid & 31;
    const int g    = blockIdx.x;
    const uint32_t smu = smem_to_u32(sm);

    // ---- stage: W1 (grid-stride, 320 float4), x, biases ----
    for (int i = tid; i < 320; i += TPB)
        ((float4*)sW1)[i] = ((const float4*)W1)[i];
    {
        const float* xg = x + (size_t)g * (NCELL * 10);
        for (int i = tid; i < NCELL * 10; i += TPB) sX[i] = xg[i];
    }
    if (tid < 128) { sB[tid] = b1[tid]; sB[128 + tid] = b2[tid]; }
    __syncthreads();

    // ---- Phase 1a: triples on 10 raw channels ----
    for (int it = tid; it < 54 * 10; it += TPB) {
        int t = it / 10, f = it - t * 10;
        unsigned pk = cTabA.v[t];
        sTripF[it] = sX[(pk & 255) * 10 + f] + sX[((pk >> 8) & 255) * 10 + f]
                   + sX[((pk >> 16) & 255) * 10 + f];
    }
    __syncthreads();
    // ---- Phase 1b: Zx = union/21 directly from trips ----
    for (int it = tid; it < NCELL * 10; it += TPB) {
        int cell = it / 10, f = it - cell * 10;
        unsigned pk = cTabD.v[cell];
        int i  = pk & 15, j = (pk >> 4) & 15;
        int bi = (pk >> 8) & 3, bj = (pk >> 12) & 3;
        const float* T = sTripF;
        float r0 = T[(i * 3 + 0) * 10 + f];
        float r1 = T[(i * 3 + 1) * 10 + f];
        float r2 = T[(i * 3 + 2) * 10 + f];
        float c0 = T[(27 + j * 3 + 0) * 10 + f];
        float c1 = T[(27 + j * 3 + 1) * 10 + f];
        float c2 = T[(27 + j * 3 + 2) * 10 + f];
        float x0 = T[((3 * bi + 0) * 3 + bj) * 10 + f];
        float x1 = T[((3 * bi + 1) * 3 + bj) * 10 + f];
        float x2 = T[((3 * bi + 2) * 3 + bj) * 10 + f];
        float rtrip = (bj == 0) ? r0 : ((bj == 1) ? r1 : r2);
        float ctrip = (bi == 0) ? c0 : ((bi == 1) ? c1 : c2);
        float agg = (r0 + r1 + r2) + (c0 + c1 + c2) + (x0 + x1 + x2)
                  - rtrip - ctrip;
        sZ[it] = agg * (1.0f / 21.0f);
    }
    __syncthreads();

    // ---- Phase 2: H1 = relu(Zx@W1 + b1) -> bf16 hi/lo into A tiles
    //      (6 stripes of 16 cells; cells >= 81 write zero pad) ----
    {
        const int kp  = tid & 63;           // k-pair, k = 2*kp
        const int grp = tid >> 6;           // 0..5, 16 cells each
        const int k   = kp << 1;
        float2 w[10];
        #pragma unroll
        for (int f = 0; f < 10; f++) w[f] = *(const float2*)(sW1 + f * 128 + k);
        const float b0 = sB[k], b1v = sB[k + 1];

        int cBeg = grp * 16;
        #pragma unroll 4
        for (int cell = cBeg; cell < cBeg + 16; cell++) {
            uint32_t h = 0u, l = 0u;
            if (cell < NCELL) {
                const float* z = sZ + cell * 10;
                float v0 = b0, v1 = b1v;
                #pragma unroll
                for (int f = 0; f < 10; f++) {
                    float zf = z[f];
                    v0 = fmaf(zf, w[f].x, v0);
                    v1 = fmaf(zf, w[f].y, v1);
                }
                v0 = v0 > 0.0f ? v0 : 0.0f;
                v1 = v1 > 0.0f ? v1 : 0.0f;
                h = cvt2bf16(v0, v1);
                float f0 = __uint_as_float(h << 16);
                float f1 = __uint_as_float(h & 0xFFFF0000u);
                l = cvt2bf16(v0 - f0, v1 - f1);
            }
            uint32_t off = (uint32_t)cell * (ASTR * 2) + (uint32_t)k * 2;
            *(uint32_t*)(smb + AHI_F * 4 + off) = h;
            *(uint32_t*)(smb + ALO_F * 4 + off) = l;
        }
    }
    __syncthreads();

    // ---- Phase 3: Y2 = H1 @ W2 via mma.sync bf16, 3-term compensated ----
    // 12 warps: warp = (4 n-tiles) x (2 m-tiles). acc = 32 regs (85-reg cap).
    {
        const int ntb  = (wid & 3) * 4;          // 4 n-tiles (8 ch each)
        const int mtb  = (wid >> 2) * 2;         // 2 m-tiles (16 rows each)
        const int arow = lane & 15;
        const int akoff = (lane & 16) ? 8 : 0;
        const int q4   = (lane & 3) * 4;
        const int nrow = lane >> 2;

        float acc[2][4][4];
        #pragma unroll
        for (int mt = 0; mt < 2; mt++)
            #pragma unroll
            for (int nt = 0; nt < 4; nt++)
                #pragma unroll
                for (int qq = 0; qq < 4; qq++) acc[mt][nt][qq] = 0.0f;

        const uint32_t aHi = smu + AHI_F * 4;
        const uint32_t aLo = smu + ALO_F * 4;
        const uint16_t* bhB = gBhi + q4;
        const uint16_t* blB = gBlo + q4;

        #pragma unroll
        for (int ks = 0; ks < 8; ks++) {
            const int k0 = ks << 4;
            uint2 bh[4], bl[4];
            #pragma unroll
            for (int nt = 0; nt < 4; nt++) {
                int n = (ntb + nt) * 8 + nrow;
                bh[nt] = *(const uint2*)(bhB + n * 128 + k0);
                bl[nt] = *(const uint2*)(blB + n * 128 + k0);
            }
            #pragma unroll
            for (int mt = 0; mt < 2; mt++) {
                uint32_t aOff = (uint32_t)((mtb + mt) * 16 + arow) * (ASTR * 2)
                              + (uint32_t)(k0 + akoff) * 2;
                uint32_t ah0, ah1, ah2, ah3, al0, al1, al2, al3;
                ldsm4(ah0, ah1, ah2, ah3, aHi + aOff);
                ldsm4(al0, al1, al2, al3, aLo + aOff);
                #pragma unroll
                for (int nt = 0; nt < 4; nt++) {
                    mma16816(acc[mt][nt], ah0, ah1, ah2, ah3, bh[nt].x, bh[nt].y);
                    mma16816(acc[mt][nt], ah0, ah1, ah2, ah3, bl[nt].x, bl[nt].y);
                    mma16816(acc[mt][nt], al0, al1, al2, al3, bh[nt].x, bh[nt].y);
                }
            }
        }
        // epilogue: scatter Y2 fragments into sH (81 rows, stride 130)
        const int rbase = lane >> 2;
        const int colq  = (lane & 3) << 1;
        #pragma unroll
        for (int mt = 0; mt < 2; mt++) {
            int row = (mtb + mt) * 16 + rbase;
            #pragma unroll
            for (int nt = 0; nt < 4; nt++) {
                int col = (ntb + nt) * 8 + colq;
                if (row < NCELL)
                    *(float2*)(sH + row * SH_STR + col) =
                        make_float2(acc[mt][nt][0], acc[mt][nt][1]);
                if (row + 8 < NCELL)
                    *(float2*)(sH + (row + 8) * SH_STR + col) =
                        make_float2(acc[mt][nt][2], acc[mt][nt][3]);
            }
        }
    }
    __syncthreads();

    // ---- Phase 4: band-blocked agg + bias + relu + pool (fused) ----
    // Pass A': item = (ch, band); 384 items, one per thread.
    if (tid < 384) {
        int ch = tid & 127, band = tid >> 7;
        const float* base = sH + (band * 27) * SH_STR + ch;
        float v[3][9];
        #pragma unroll
        for (int r = 0; r < 3; r++)
            #pragma unroll
            for (int j = 0; j < 9; j++)
                v[r][j] = base[(r * 9 + j) * SH_STR];
        #pragma unroll
        for (int r = 0; r < 3; r++)
            #pragma unroll
            for (int bj = 0; bj < 3; bj++)
                sm[RT_F + (band * 9 + r * 3 + bj) * 128 + ch] =
                    v[r][3 * bj] + v[r][3 * bj + 1] + v[r][3 * bj + 2];
        #pragma unroll
        for (int j = 0; j < 9; j++)
            sm[CT_F + (band * 9 + j) * 128 + ch] = v[0][j] + v[1][j] + v[2][j];
    }
    __syncthreads();

    // Pass C': rowsums/boxsums derived from RT; evaluate 27 cells, relu+pool.
    if (tid < 384) {
        int ch = tid & 127, band = tid >> 7;
        float bias = sB[128 + ch];
        float rt[3][3];
        #pragma unroll
        for (int r = 0; r < 3; r++)
            #pragma unroll
            for (int bj = 0; bj < 3; bj++)
                rt[r][bj] = sm[RT_F + (band * 9 + r * 3 + bj) * 128 + ch];
        float RS[3], BX[3];
        #pragma unroll
        for (int r = 0; r < 3; r++)
            RS[r] = rt[r][0] + rt[r][1] + rt[r][2];
        #pragma unroll
        for (int bj = 0; bj < 3; bj++)
            BX[bj] = rt[0][bj] + rt[1][bj] + rt[2][bj];
        float Cj[9], ctOwn[9];
        #pragma unroll
        for (int j = 0; j < 9; j++) {
            float c0 = sm[CT_F + j * 128 + ch];
            float c1 = sm[CT_F + (9 + j) * 128 + ch];
            float c2 = sm[CT_F + (18 + j) * 128 + ch];
            Cj[j] = c0 + c1 + c2;
            ctOwn[j] = (band == 0) ? c0 : ((band == 1) ? c1 : c2);
        }
        float acc = 0.0f;
        #pragma unroll
        for (int r = 0; r < 3; r++) {
            #pragma unroll
            for (int bj = 0; bj < 3; bj++) {
                float common = RS[r] + BX[bj] - rt[r][bj];
                #pragma unroll
                for (int jj = 0; jj < 3; jj++) {
                    int j = bj * 3 + jj;
                    float val = (common + Cj[j] - ctOwn[j]) * (1.0f / 21.0f) + bias;
                    acc += val > 0.0f ? val : 0.0f;
                }
            }
        }
        sPoolP[band * 128 + ch] = acc;
    }
    __syncthreads();
    if (tid < 128)
        sP[tid] = (sPoolP[tid] + sPoolP[128 + tid] + sPoolP[256 + tid])
                * (1.0f / 81.0f);
    __syncthreads();

    // ---- Phase 5: heads, k-split across 208 threads ----
    {
        int half = (tid >= 128) ? 1 : 0;
        int idx  = half ? tid - 128 : tid;
        if (idx < 104 && tid < 256) {
            const float* W; const float* bb; int nc, col;
            if (idx < 4)       { W = Wa; bb = ba; nc = 4;  col = idx; }
            else if (idx < 85) { W = Wc; bb = bc; nc = 81; col = idx - 4; }
            else if (idx < 94) { W = Wn; bb = bn; nc = 9;  col = idx - 85; }
            else               { W = Wt; bb = bt; nc = 10; col = idx - 94; }
            float acc = half ? 0.0f : bb[col];
            int kb = half << 6;
            #pragma unroll 16
            for (int k = 0; k < 64; k++)
                acc = fmaf(sP[kb + k], W[(kb + k) * nc + col], acc);
            sHeadP[half * 104 + idx] = acc;
        }
    }
    __syncthreads();
    if (tid < 104) {
        int col; size_t off;
        if (tid < 4)       { col = tid;      off = (size_t)g * 4 + col; }
        else if (tid < 85) { col = tid - 4;  off = 8192u   + (size_t)g * 81 + col; }
        else if (tid < 94) { col = tid - 85; off = 174080u + (size_t)g * 9  + col; }
        else               { col = tid - 94; off = 192512u + (size_t)g * 10 + col; }
        out[off] = sHeadP[tid] + sHeadP[104 + tid];
    }
}

extern "C" void kernel_launch(void* const* d_in, const int* in_sizes, int n_in,
                              void* d_out, int out_size)
{
    const float* x  = (const float*)d_in[0];
    const float* W1 = (const float*)d_in[3];
    const float* b1 = (const float*)d_in[4];
    const float* W2 = (const float*)d_in[5];
    const float* b2 = (const float*)d_in[6];
    const float* Wa = (const float*)d_in[7];
    const float* ba = (const float*)d_in[8];
    const float* Wc = (const float*)d_in[9];
    const float* bc = (const float*)d_in[10];
    const float* Wn = (const float*)d_in[11];
    const float* bn = (const float*)d_in[12];
    const float* Wt = (const float*)d_in[13];
    const float* bt = (const float*)d_in[14];
    float* out = (float*)d_out;

    const int nGraphs = in_sizes[0] / (NCELL * 10);   // 2048
    const size_t smemBytes = (size_t)SM_FLOATS * sizeof(float);  // ~105 KB

    prep_w2_kernel<<<16, 256>>>(W2);

    cudaFuncSetAttribute(sudoku_gnn_kernel,
                         cudaFuncAttributeMaxDynamicSharedMemorySize,
                         (int)smemBytes);
    sudoku_gnn_kernel<<<nGraphs, TPB, smemBytes>>>(
        x, W1, b1, b2, Wa, ba, Wc, bc, Wn, bn, Wt, bt, out);
}

// round 15
// speedup vs baseline: 1.1482x; 1.1482x over previous
#include <cuda_runtime.h>
#include <cuda_fp16.h>
#include <stdint.h>

#define NCELL 81
#define TPB   256

// fp16 A tile: row stride 136 halves (272 B), 16B-aligned, ldmatrix conflict-free
#define ASTR  136
// ---- float-index smem layout (23812 floats = 95248 B -> 2 CTAs/SM) ----
#define AHI_F 0        // A fp16 96 x 136 halves (6528 f)
#define SH_F  6528     // Y2 fp32 81 x 130 (10530 f, +2 pad)
#define SH_STR 130
#define SW1_F 17060    // W1 10x128 (1280)
#define SX_F  18340    // x 81x10 (816)
#define SZ_F  19156    // A_hat@x 81x10 (816)
#define SP_F  19972    // pooled (128)
#define SB_F  20100    // b1|b2 (256)
#define CT_F  20356    // phase-4 coltrip 27x128 (3456)
#define SM_FLOATS 23812
// scratch overlapping the (temporally dead) A region:
#define TRIP_F  0      // phase 1 trips (540 f)
#define RT_F    0      // phase 4 rowtrip 27x128 = 3456
#define POOLP_F 3456   // pool partials 3 x 128 = 384
#define HEADP_F 3840   // head partials 208

// ---- prepacked W2 (fp16 hi/lo) in device-global, B-fragment quad order ----
// layout: [n][g][q][4] halves, quad q holds k = 16g + {2q, 2q+1, 2q+8, 2q+9}
__device__ __align__(16) uint16_t gBhi[128 * 128];
__device__ __align__(16) uint16_t gBlo[128 * 128];

__global__ void prep_w2_kernel(const float* __restrict__ W2) {
    int idx = blockIdx.x * blockDim.x + threadIdx.x;   // 4096 quads
    if (idx >= 4096) return;
    int n = idx >> 5, g = (idx >> 2) & 7, q = idx & 3;
    int kb = 16 * g + 2 * q;
    int ks[4] = { kb, kb + 1, kb + 8, kb + 9 };
    uint16_t h[4], l[4];
    #pragma unroll
    for (int e = 0; e < 4; e++) {
        float w = W2[ks[e] * 128 + n];
        __half hb = __float2half_rn(w);
        float fh = __half2float(hb);
        __half lb = __float2half_rn(w - fh);
        h[e] = __half_as_ushort(hb);
        l[e] = __half_as_ushort(lb);
    }
    int off = n * 128 + g * 16 + q * 4;
    uint64_t hv, lv;
    memcpy(&hv, h, 8);
    memcpy(&lv, l, 8);
    *(uint64_t*)(gBhi + off) = hv;
    *(uint64_t*)(gBlo + off) = lv;
}

// ================= constexpr index tables (phase 1) =========================
struct U54 { unsigned v[54]; };
struct U81 { unsigned v[81]; };

static constexpr U54 mkA() {
    U54 r{};
    for (int t = 0; t < 54; t++) {
        int c0 = 0, c1 = 0, c2 = 0;
        if (t < 27) { int i = t / 3, bj = t % 3, base = i * 9 + bj * 3;
                      c0 = base; c1 = base + 1; c2 = base + 2; }
        else        { int u = t - 27, j = u / 3, bi = u % 3, base = bi * 27 + j;
                      c0 = base; c1 = base + 9; c2 = base + 18; }
        r.v[t] = (unsigned)(c0 | (c1 << 8) | (c2 << 16));
    }
    return r;
}
// cell -> i | j<<4 | bi<<8 | bj<<12
static constexpr U81 mkD() {
    U81 r{};
    for (int cell = 0; cell < 81; cell++) {
        int i = cell / 9, j = cell % 9, bi = i / 3, bj = j / 3;
        r.v[cell] = (unsigned)(i | (j << 4) | (bi << 8) | (bj << 12));
    }
    return r;
}
__constant__ U54 cTabA = mkA();
__constant__ U81 cTabD = mkD();

// ================= PTX helpers ==============================================
__device__ __forceinline__ uint32_t smem_to_u32(const void* p) {
    uint32_t a;
    asm("{ .reg .u64 t; cvta.to.shared.u64 t, %1; cvt.u32.u64 %0, t; }"
        : "=r"(a) : "l"(p));
    return a;
}
// pack two floats to fp16x2 (v0 -> low half, v1 -> high half)
__device__ __forceinline__ uint32_t cvt2f16(float v0, float v1) {
    uint32_t r;
    asm("cvt.rn.f16x2.f32 %0, %1, %2;" : "=r"(r) : "f"(v1), "f"(v0));
    return r;
}
__device__ __forceinline__ void ldsm4(uint32_t& r0, uint32_t& r1,
                                      uint32_t& r2, uint32_t& r3, uint32_t addr) {
    asm volatile("ldmatrix.sync.aligned.m8n8.x4.shared.b16 {%0,%1,%2,%3}, [%4];"
                 : "=r"(r0), "=r"(r1), "=r"(r2), "=r"(r3) : "r"(addr));
}
__device__ __forceinline__ void mma16816(float* c, uint32_t a0, uint32_t a1,
                                         uint32_t a2, uint32_t a3,
                                         uint32_t b0, uint32_t b1) {
    asm volatile(
        "mma.sync.aligned.m16n8k16.row.col.f32.f16.f16.f32 "
        "{%0,%1,%2,%3}, {%4,%5,%6,%7}, {%8,%9}, {%0,%1,%2,%3};"
        : "+f"(c[0]), "+f"(c[1]), "+f"(c[2]), "+f"(c[3])
        : "r"(a0), "r"(a1), "r"(a2), "r"(a3), "r"(b0), "r"(b1));
}

// ================= main kernel ==============================================
__global__ __launch_bounds__(TPB, 2)
void sudoku_gnn_kernel(const float* __restrict__ x,
                       const float* __restrict__ W1, const float* __restrict__ b1,
                       const float* __restrict__ b2,
                       const float* __restrict__ Wa, const float* __restrict__ ba,
                       const float* __restrict__ Wc, const float* __restrict__ bc,
                       const float* __restrict__ Wn, const float* __restrict__ bn,
                       const float* __restrict__ Wt, const float* __restrict__ bt,
                       float* __restrict__ out)
{
    extern __shared__ float sm[];
    char*  smb = (char*)sm;
    float* sH  = sm + SH_F;
    float* sW1 = sm + SW1_F;
    float* sX  = sm + SX_F;
    float* sZ  = sm + SZ_F;
    float* sP  = sm + SP_F;
    float* sB  = sm + SB_F;
    float* sTripF = sm + TRIP_F;
    float* sPoolP = sm + POOLP_F;
    float* sHeadP = sm + HEADP_F;

    const int tid  = threadIdx.x;
    const int wid  = tid >> 5;
    const int lane = tid & 31;
    const int g    = blockIdx.x;
    const uint32_t smu = smem_to_u32(sm);

    // ---- stage: W1 (grid-stride, 320 float4), x, biases ----
    for (int i = tid; i < 320; i += TPB)
        ((float4*)sW1)[i] = ((const float4*)W1)[i];
    {
        const float* xg = x + (size_t)g * (NCELL * 10);
        for (int i = tid; i < NCELL * 10; i += TPB) sX[i] = xg[i];
    }
    if (tid < 128) { sB[tid] = b1[tid]; sB[128 + tid] = b2[tid]; }
    __syncthreads();

    // ---- Phase 1a: triples on 10 raw channels ----
    for (int it = tid; it < 54 * 10; it += TPB) {
        int t = it / 10, f = it - t * 10;
        unsigned pk = cTabA.v[t];
        sTripF[it] = sX[(pk & 255) * 10 + f] + sX[((pk >> 8) & 255) * 10 + f]
                   + sX[((pk >> 16) & 255) * 10 + f];
    }
    __syncthreads();
    // ---- Phase 1b: Zx = union/21 directly from trips ----
    for (int it = tid; it < NCELL * 10; it += TPB) {
        int cell = it / 10, f = it - cell * 10;
        unsigned pk = cTabD.v[cell];
        int i  = pk & 15, j = (pk >> 4) & 15;
        int bi = (pk >> 8) & 3, bj = (pk >> 12) & 3;
        const float* T = sTripF;
        float r0 = T[(i * 3 + 0) * 10 + f];
        float r1 = T[(i * 3 + 1) * 10 + f];
        float r2 = T[(i * 3 + 2) * 10 + f];
        float c0 = T[(27 + j * 3 + 0) * 10 + f];
        float c1 = T[(27 + j * 3 + 1) * 10 + f];
        float c2 = T[(27 + j * 3 + 2) * 10 + f];
        float x0 = T[((3 * bi + 0) * 3 + bj) * 10 + f];
        float x1 = T[((3 * bi + 1) * 3 + bj) * 10 + f];
        float x2 = T[((3 * bi + 2) * 3 + bj) * 10 + f];
        float rtrip = (bj == 0) ? r0 : ((bj == 1) ? r1 : r2);
        float ctrip = (bi == 0) ? c0 : ((bi == 1) ? c1 : c2);
        float agg = (r0 + r1 + r2) + (c0 + c1 + c2) + (x0 + x1 + x2)
                  - rtrip - ctrip;
        sZ[it] = agg * (1.0f / 21.0f);
    }
    __syncthreads();

    // ---- Phase 2: H1 = relu(Zx@W1 + b1) -> fp16 into A tile
    //      (24-cell stripes cover 96 rows; cells >= 81 write zero pad) ----
    {
        const int kp  = tid & 63;           // k-pair, k = 2*kp
        const int grp = tid >> 6;           // 0..3, 24 cells each
        const int k   = kp << 1;
        float2 w[10];
        #pragma unroll
        for (int f = 0; f < 10; f++) w[f] = *(const float2*)(sW1 + f * 128 + k);
        const float b0 = sB[k], b1v = sB[k + 1];

        int cBeg = grp * 24;
        #pragma unroll 4
        for (int cell = cBeg; cell < cBeg + 24; cell++) {
            uint32_t h = 0u;
            if (cell < NCELL) {
                const float* z = sZ + cell * 10;
                float v0 = b0, v1 = b1v;
                #pragma unroll
                for (int f = 0; f < 10; f++) {
                    float zf = z[f];
                    v0 = fmaf(zf, w[f].x, v0);
                    v1 = fmaf(zf, w[f].y, v1);
                }
                v0 = v0 > 0.0f ? v0 : 0.0f;
                v1 = v1 > 0.0f ? v1 : 0.0f;
                h = cvt2f16(v0, v1);
            }
            uint32_t off = (uint32_t)cell * (ASTR * 2) + (uint32_t)k * 2;
            *(uint32_t*)(smb + AHI_F * 4 + off) = h;
        }
    }
    __syncthreads();

    // ---- Phase 3: Y2 = H1 @ W2 via mma.sync fp16, 2-term (Ah*Bh + Ah*Bl) ----
    {
        const int ntb  = (wid & 3) * 4;          // 4 n-tiles (8 ch each)
        const int mtb  = (wid >> 2) * 3;         // 3 m-tiles (16 rows each)
        const int arow = lane & 15;
        const int akoff = (lane & 16) ? 8 : 0;
        const int q4   = (lane & 3) * 4;
        const int nrow = lane >> 2;

        float acc[3][4][4];
        #pragma unroll
        for (int mt = 0; mt < 3; mt++)
            #pragma unroll
            for (int nt = 0; nt < 4; nt++)
                #pragma unroll
                for (int qq = 0; qq < 4; qq++) acc[mt][nt][qq] = 0.0f;

        const uint32_t aHi = smu + AHI_F * 4;
        const uint16_t* bhB = gBhi + q4;
        const uint16_t* blB = gBlo + q4;

        #pragma unroll
        for (int ks = 0; ks < 8; ks++) {
            const int k0 = ks << 4;
            uint2 bh[4], bl[4];
            #pragma unroll
            for (int nt = 0; nt < 4; nt++) {
                int n = (ntb + nt) * 8 + nrow;
                bh[nt] = *(const uint2*)(bhB + n * 128 + k0);
                bl[nt] = *(const uint2*)(blB + n * 128 + k0);
            }
            #pragma unroll
            for (int mt = 0; mt < 3; mt++) {
                uint32_t aOff = (uint32_t)((mtb + mt) * 16 + arow) * (ASTR * 2)
                              + (uint32_t)(k0 + akoff) * 2;
                uint32_t ah0, ah1, ah2, ah3;
                ldsm4(ah0, ah1, ah2, ah3, aHi + aOff);
                #pragma unroll
                for (int nt = 0; nt < 4; nt++) {
                    mma16816(acc[mt][nt], ah0, ah1, ah2, ah3, bh[nt].x, bh[nt].y);
                    mma16816(acc[mt][nt], ah0, ah1, ah2, ah3, bl[nt].x, bl[nt].y);
                }
            }
        }
        // epilogue: scatter Y2 fragments into sH (81 rows, stride 130)
        const int rbase = lane >> 2;
        const int colq  = (lane & 3) << 1;
        #pragma unroll
        for (int mt = 0; mt < 3; mt++) {
            int row = (mtb + mt) * 16 + rbase;
            #pragma unroll
            for (int nt = 0; nt < 4; nt++) {
                int col = (ntb + nt) * 8 + colq;
                if (row < NCELL)
                    *(float2*)(sH + row * SH_STR + col) =
                        make_float2(acc[mt][nt][0], acc[mt][nt][1]);
                if (row + 8 < NCELL)
                    *(float2*)(sH + (row + 8) * SH_STR + col) =
                        make_float2(acc[mt][nt][2], acc[mt][nt][3]);
            }
        }
    }
    __syncthreads();

    // ---- Phase 4: band-blocked agg + bias + relu + pool (fused) ----
    // Pass A': item = (ch, band). Read band's 27 cells once; write rowtrips
    // (RT) and coltrips (CT); rowsums/boxsums derived in pass C'.
    for (int it = tid; it < 384; it += TPB) {
        int ch = it & 127, band = it >> 7;
        const float* base = sH + (band * 27) * SH_STR + ch;
        float v[3][9];
        #pragma unroll
        for (int r = 0; r < 3; r++)
            #pragma unroll
            for (int j = 0; j < 9; j++)
                v[r][j] = base[(r * 9 + j) * SH_STR];
        #pragma unroll
        for (int r = 0; r < 3; r++)
            #pragma unroll
            for (int bj = 0; bj < 3; bj++)
                sm[RT_F + (band * 9 + r * 3 + bj) * 128 + ch] =
                    v[r][3 * bj] + v[r][3 * bj + 1] + v[r][3 * bj + 2];
        #pragma unroll
        for (int j = 0; j < 9; j++)
            sm[CT_F + (band * 9 + j) * 128 + ch] = v[0][j] + v[1][j] + v[2][j];
    }
    __syncthreads();

    // Pass C': rowsums/boxsums derived from RT; evaluate 27 cells, relu+pool.
    for (int it = tid; it < 384; it += TPB) {
        int ch = it & 127, band = it >> 7;
        float bias = sB[128 + ch];
        float rt[3][3];
        #pragma unroll
        for (int r = 0; r < 3; r++)
            #pragma unroll
            for (int bj = 0; bj < 3; bj++)
                rt[r][bj] = sm[RT_F + (band * 9 + r * 3 + bj) * 128 + ch];
        float RS[3], BX[3];
        #pragma unroll
        for (int r = 0; r < 3; r++)
            RS[r] = rt[r][0] + rt[r][1] + rt[r][2];
        #pragma unroll
        for (int bj = 0; bj < 3; bj++)
            BX[bj] = rt[0][bj] + rt[1][bj] + rt[2][bj];
        float Cj[9], ctOwn[9];
        #pragma unroll
        for (int j = 0; j < 9; j++) {
            float c0 = sm[CT_F + j * 128 + ch];
            float c1 = sm[CT_F + (9 + j) * 128 + ch];
            float c2 = sm[CT_F + (18 + j) * 128 + ch];
            Cj[j] = c0 + c1 + c2;
            ctOwn[j] = (band == 0) ? c0 : ((band == 1) ? c1 : c2);
        }
        float acc = 0.0f;
        #pragma unroll
        for (int r = 0; r < 3; r++) {
            #pragma unroll
            for (int bj = 0; bj < 3; bj++) {
                float common = RS[r] + BX[bj] - rt[r][bj];
                #pragma unroll
                for (int jj = 0; jj < 3; jj++) {
                    int j = bj * 3 + jj;
                    float val = (common + Cj[j] - ctOwn[j]) * (1.0f / 21.0f) + bias;
                    acc += val > 0.0f ? val : 0.0f;
                }
            }
        }
        sPoolP[band * 128 + ch] = acc;
    }
    __syncthreads();
    if (tid < 128)
        sP[tid] = (sPoolP[tid] + sPoolP[128 + tid] + sPoolP[256 + tid])
                * (1.0f / 81.0f);
    __syncthreads();

    // ---- Phase 5: heads, k-split across 208 threads ----
    {
        int half = (tid >= 128) ? 1 : 0;
        int idx  = half ? tid - 128 : tid;
        if (idx < 104) {
            const float* W; const float* bb; int nc, col;
            if (idx < 4)       { W = Wa; bb = ba; nc = 4;  col = idx; }
            else if (idx < 85) { W = Wc; bb = bc; nc = 81; col = idx - 4; }
            else if (idx < 94) { W = Wn; bb = bn; nc = 9;  col = idx - 85; }
            else               { W = Wt; bb = bt; nc = 10; col = idx - 94; }
            float acc = half ? 0.0f : bb[col];
            int kb = half << 6;
            #pragma unroll 16
            for (int k = 0; k < 64; k++)
                acc = fmaf(sP[kb + k], W[(kb + k) * nc + col], acc);
            sHeadP[half * 104 + idx] = acc;
        }
    }
    __syncthreads();
    if (tid < 104) {
        int col; size_t off;
        if (tid < 4)       { col = tid;      off = (size_t)g * 4 + col; }
        else if (tid < 85) { col = tid - 4;  off = 8192u   + (size_t)g * 81 + col; }
        else if (tid < 94) { col = tid - 85; off = 174080u + (size_t)g * 9  + col; }
        else               { col = tid - 94; off = 192512u + (size_t)g * 10 + col; }
        out[off] = sHeadP[tid] + sHeadP[104 + tid];
    }
}

extern "C" void kernel_launch(void* const* d_in, const int* in_sizes, int n_in,
                              void* d_out, int out_size)
{
    const float* x  = (const float*)d_in[0];
    const float* W1 = (const float*)d_in[3];
    const float* b1 = (const float*)d_in[4];
    const float* W2 = (const float*)d_in[5];
    const float* b2 = (const float*)d_in[6];
    const float* Wa = (const float*)d_in[7];
    const float* ba = (const float*)d_in[8];
    const float* Wc = (const float*)d_in[9];
    const float* bc = (const float*)d_in[10];
    const float* Wn = (const float*)d_in[11];
    const float* bn = (const float*)d_in[12];
    const float* Wt = (const float*)d_in[13];
    const float* bt = (const float*)d_in[14];
    float* out = (float*)d_out;

    const int nGraphs = in_sizes[0] / (NCELL * 10);   // 2048
    const size_t smemBytes = (size_t)SM_FLOATS * sizeof(float);  // ~95 KB

    prep_w2_kernel<<<16, 256>>>(W2);

    cudaFuncSetAttribute(sudoku_gnn_kernel,
                         cudaFuncAttributeMaxDynamicSharedMemorySize,
                         (int)smemBytes);
    sudoku_gnn_kernel<<<nGraphs, TPB, smemBytes>>>(
        x, W1, b1, b2, Wa, ba, Wc, bc, Wn, bn, Wt, bt, out);
}

// round 16
// speedup vs baseline: 1.2666x; 1.1031x over previous
#include <cuda_runtime.h>
#include <cuda_fp16.h>
#include <stdint.h>

#define NCELL 81
#define TPB   256

// fp16 A tile: row stride 136 halves (272 B), 16B-aligned, ldmatrix conflict-free
#define ASTR  136
// ---- float-index smem layout (15332 floats = 61328 B) ----
#define AHI_F 0        // A fp16 96 x 136 halves (6528 f)
#define SHH_F 6528     // Y2 half2 81 x 68 words (5508 f)
#define SHH_STR 68
#define SW1_F 12036    // W1 10x128 (1280)
#define SX_F  13316    // x 81x10 (816)
#define SZ_F  14132    // A_hat@x 81x10 (816)
#define SP_F  14948    // pooled (128)
#define SB_F  15076    // b1|b2 (256)
#define SM_FLOATS 15332
// scratch overlapping the (temporally dead) A region:
#define TRIP_F  0      // phase 1 trips (540 f)
#define CT_F    0      // phase 4 coltrip float2 [band*9+j][cp]: 27*64*2 = 3456 f
#define POOLP_F 3456   // pool partials float2: 3*64*2 = 384 f
#define HEADP_F 3840   // head partials 208 f

// ---- prepacked W2 (fp16 hi/lo) in device-global, B-fragment quad order ----
__device__ __align__(16) uint16_t gBhi[128 * 128];
__device__ __align__(16) uint16_t gBlo[128 * 128];

__global__ void prep_w2_kernel(const float* __restrict__ W2) {
    int idx = blockIdx.x * blockDim.x + threadIdx.x;   // 4096 quads
    if (idx >= 4096) return;
    int n = idx >> 5, g = (idx >> 2) & 7, q = idx & 3;
    int kb = 16 * g + 2 * q;
    int ks[4] = { kb, kb + 1, kb + 8, kb + 9 };
    uint16_t h[4], l[4];
    #pragma unroll
    for (int e = 0; e < 4; e++) {
        float w = W2[ks[e] * 128 + n];
        __half hb = __float2half_rn(w);
        float fh = __half2float(hb);
        __half lb = __float2half_rn(w - fh);
        h[e] = __half_as_ushort(hb);
        l[e] = __half_as_ushort(lb);
    }
    int off = n * 128 + g * 16 + q * 4;
    uint64_t hv, lv;
    memcpy(&hv, h, 8);
    memcpy(&lv, l, 8);
    *(uint64_t*)(gBhi + off) = hv;
    *(uint64_t*)(gBlo + off) = lv;
}

// ================= constexpr index tables (phase 1) =========================
struct U54 { unsigned v[54]; };
struct U81 { unsigned v[81]; };

static constexpr U54 mkA() {
    U54 r{};
    for (int t = 0; t < 54; t++) {
        int c0 = 0, c1 = 0, c2 = 0;
        if (t < 27) { int i = t / 3, bj = t % 3, base = i * 9 + bj * 3;
                      c0 = base; c1 = base + 1; c2 = base + 2; }
        else        { int u = t - 27, j = u / 3, bi = u % 3, base = bi * 27 + j;
                      c0 = base; c1 = base + 9; c2 = base + 18; }
        r.v[t] = (unsigned)(c0 | (c1 << 8) | (c2 << 16));
    }
    return r;
}
static constexpr U81 mkD() {
    U81 r{};
    for (int cell = 0; cell < 81; cell++) {
        int i = cell / 9, j = cell % 9, bi = i / 3, bj = j / 3;
        r.v[cell] = (unsigned)(i | (j << 4) | (bi << 8) | (bj << 12));
    }
    return r;
}
__constant__ U54 cTabA = mkA();
__constant__ U81 cTabD = mkD();

// ================= PTX helpers ==============================================
__device__ __forceinline__ uint32_t smem_to_u32(const void* p) {
    uint32_t a;
    asm("{ .reg .u64 t; cvta.to.shared.u64 t, %1; cvt.u32.u64 %0, t; }"
        : "=r"(a) : "l"(p));
    return a;
}
__device__ __forceinline__ uint32_t cvt2f16(float v0, float v1) {
    uint32_t r;
    asm("cvt.rn.f16x2.f32 %0, %1, %2;" : "=r"(r) : "f"(v1), "f"(v0));
    return r;
}
__device__ __forceinline__ float2 h2f2(uint32_t u) {
    __half2 h = *(__half2*)&u;
    return __half22float2(h);
}
__device__ __forceinline__ void ldsm4(uint32_t& r0, uint32_t& r1,
                                      uint32_t& r2, uint32_t& r3, uint32_t addr) {
    asm volatile("ldmatrix.sync.aligned.m8n8.x4.shared.b16 {%0,%1,%2,%3}, [%4];"
                 : "=r"(r0), "=r"(r1), "=r"(r2), "=r"(r3) : "r"(addr));
}
__device__ __forceinline__ void mma16816(float* c, uint32_t a0, uint32_t a1,
                                         uint32_t a2, uint32_t a3,
                                         uint32_t b0, uint32_t b1) {
    asm volatile(
        "mma.sync.aligned.m16n8k16.row.col.f32.f16.f16.f32 "
        "{%0,%1,%2,%3}, {%4,%5,%6,%7}, {%8,%9}, {%0,%1,%2,%3};"
        : "+f"(c[0]), "+f"(c[1]), "+f"(c[2]), "+f"(c[3])
        : "r"(a0), "r"(a1), "r"(a2), "r"(a3), "r"(b0), "r"(b1));
}

// ================= main kernel ==============================================
__global__ __launch_bounds__(TPB, 2)
void sudoku_gnn_kernel(const float* __restrict__ x,
                       const float* __restrict__ W1, const float* __restrict__ b1,
                       const float* __restrict__ b2,
                       const float* __restrict__ Wa, const float* __restrict__ ba,
                       const float* __restrict__ Wc, const float* __restrict__ bc,
                       const float* __restrict__ Wn, const float* __restrict__ bn,
                       const float* __restrict__ Wt, const float* __restrict__ bt,
                       float* __restrict__ out)
{
    extern __shared__ float sm[];
    char*     smb = (char*)sm;
    uint32_t* sHH = (uint32_t*)(sm + SHH_F);
    float*    sW1 = sm + SW1_F;
    float*    sX  = sm + SX_F;
    float*    sZ  = sm + SZ_F;
    float*    sP  = sm + SP_F;
    float*    sB  = sm + SB_F;
    float*    sTripF = sm + TRIP_F;
    float2*   sCT   = (float2*)(sm + CT_F);
    float2*   sPoolP = (float2*)(sm + POOLP_F);
    float*    sHeadP = sm + HEADP_F;

    const int tid  = threadIdx.x;
    const int wid  = tid >> 5;
    const int lane = tid & 31;
    const int g    = blockIdx.x;
    const uint32_t smu = smem_to_u32(sm);

    // ---- stage: W1 (grid-stride, 320 float4), x, biases ----
    for (int i = tid; i < 320; i += TPB)
        ((float4*)sW1)[i] = ((const float4*)W1)[i];
    {
        const float* xg = x + (size_t)g * (NCELL * 10);
        for (int i = tid; i < NCELL * 10; i += TPB) sX[i] = xg[i];
    }
    if (tid < 128) { sB[tid] = b1[tid]; sB[128 + tid] = b2[tid]; }
    __syncthreads();

    // ---- Phase 1a: triples on 10 raw channels ----
    for (int it = tid; it < 54 * 10; it += TPB) {
        int t = it / 10, f = it - t * 10;
        unsigned pk = cTabA.v[t];
        sTripF[it] = sX[(pk & 255) * 10 + f] + sX[((pk >> 8) & 255) * 10 + f]
                   + sX[((pk >> 16) & 255) * 10 + f];
    }
    __syncthreads();
    // ---- Phase 1b: Zx = union/21 directly from trips ----
    for (int it = tid; it < NCELL * 10; it += TPB) {
        int cell = it / 10, f = it - cell * 10;
        unsigned pk = cTabD.v[cell];
        int i  = pk & 15, j = (pk >> 4) & 15;
        int bi = (pk >> 8) & 3, bj = (pk >> 12) & 3;
        const float* T = sTripF;
        float r0 = T[(i * 3 + 0) * 10 + f];
        float r1 = T[(i * 3 + 1) * 10 + f];
        float r2 = T[(i * 3 + 2) * 10 + f];
        float c0 = T[(27 + j * 3 + 0) * 10 + f];
        float c1 = T[(27 + j * 3 + 1) * 10 + f];
        float c2 = T[(27 + j * 3 + 2) * 10 + f];
        float x0 = T[((3 * bi + 0) * 3 + bj) * 10 + f];
        float x1 = T[((3 * bi + 1) * 3 + bj) * 10 + f];
        float x2 = T[((3 * bi + 2) * 3 + bj) * 10 + f];
        float rtrip = (bj == 0) ? r0 : ((bj == 1) ? r1 : r2);
        float ctrip = (bi == 0) ? c0 : ((bi == 1) ? c1 : c2);
        float agg = (r0 + r1 + r2) + (c0 + c1 + c2) + (x0 + x1 + x2)
                  - rtrip - ctrip;
        sZ[it] = agg * (1.0f / 21.0f);
    }
    __syncthreads();

    // ---- Phase 2: H1 = relu(Zx@W1 + b1) -> fp16 into A tile ----
    {
        const int kp  = tid & 63;           // k-pair, k = 2*kp
        const int grp = tid >> 6;           // 0..3, 24 cells each
        const int k   = kp << 1;
        float2 w[10];
        #pragma unroll
        for (int f = 0; f < 10; f++) w[f] = *(const float2*)(sW1 + f * 128 + k);
        const float b0 = sB[k], b1v = sB[k + 1];

        int cBeg = grp * 24;
        #pragma unroll 4
        for (int cell = cBeg; cell < cBeg + 24; cell++) {
            uint32_t h = 0u;
            if (cell < NCELL) {
                const float* z = sZ + cell * 10;
                float v0 = b0, v1 = b1v;
                #pragma unroll
                for (int f = 0; f < 10; f++) {
                    float zf = z[f];
                    v0 = fmaf(zf, w[f].x, v0);
                    v1 = fmaf(zf, w[f].y, v1);
                }
                v0 = v0 > 0.0f ? v0 : 0.0f;
                v1 = v1 > 0.0f ? v1 : 0.0f;
                h = cvt2f16(v0, v1);
            }
            uint32_t off = (uint32_t)cell * (ASTR * 2) + (uint32_t)k * 2;
            *(uint32_t*)(smb + AHI_F * 4 + off) = h;
        }
    }
    __syncthreads();

    // ---- Phase 3: Y2 = H1 @ W2 via mma.sync fp16, 2-term (Ah*Bh + Ah*Bl) ----
    {
        const int ntb  = (wid & 3) * 4;          // 4 n-tiles (8 ch each)
        const int mtb  = (wid >> 2) * 3;         // 3 m-tiles (16 rows each)
        const int arow = lane & 15;
        const int akoff = (lane & 16) ? 8 : 0;
        const int q4   = (lane & 3) * 4;
        const int nrow = lane >> 2;

        float acc[3][4][4];
        #pragma unroll
        for (int mt = 0; mt < 3; mt++)
            #pragma unroll
            for (int nt = 0; nt < 4; nt++)
                #pragma unroll
                for (int qq = 0; qq < 4; qq++) acc[mt][nt][qq] = 0.0f;

        const uint32_t aHi = smu + AHI_F * 4;
        const uint16_t* bhB = gBhi + q4;
        const uint16_t* blB = gBlo + q4;

        #pragma unroll
        for (int ks = 0; ks < 8; ks++) {
            const int k0 = ks << 4;
            uint2 bh[4], bl[4];
            #pragma unroll
            for (int nt = 0; nt < 4; nt++) {
                int n = (ntb + nt) * 8 + nrow;
                bh[nt] = *(const uint2*)(bhB + n * 128 + k0);
                bl[nt] = *(const uint2*)(blB + n * 128 + k0);
            }
            #pragma unroll
            for (int mt = 0; mt < 3; mt++) {
                uint32_t aOff = (uint32_t)((mtb + mt) * 16 + arow) * (ASTR * 2)
                              + (uint32_t)(k0 + akoff) * 2;
                uint32_t ah0, ah1, ah2, ah3;
                ldsm4(ah0, ah1, ah2, ah3, aHi + aOff);
                #pragma unroll
                for (int nt = 0; nt < 4; nt++) {
                    mma16816(acc[mt][nt], ah0, ah1, ah2, ah3, bh[nt].x, bh[nt].y);
                    mma16816(acc[mt][nt], ah0, ah1, ah2, ah3, bl[nt].x, bl[nt].y);
                }
            }
        }
        // epilogue: pack channel pairs to half2, store into sHH (stride 68)
        const int rbase = lane >> 2;
        const int cpq   = lane & 3;              // colPair within n-tile
        #pragma unroll
        for (int mt = 0; mt < 3; mt++) {
            int row = (mtb + mt) * 16 + rbase;
            #pragma unroll
            for (int nt = 0; nt < 4; nt++) {
                int cp = (ntb + nt) * 4 + cpq;   // channel pair index 0..63
                if (row < NCELL)
                    sHH[row * SHH_STR + cp] = cvt2f16(acc[mt][nt][0], acc[mt][nt][1]);
                if (row + 8 < NCELL)
                    sHH[(row + 8) * SHH_STR + cp] = cvt2f16(acc[mt][nt][2], acc[mt][nt][3]);
            }
        }
    }
    __syncthreads();

    // ---- Phase 4: fused band agg + bias + relu + pool.
    //      Rowtrips live in registers across ONE barrier; coltrips via smem. --
    {
        const int cp   = tid & 63;
        const int band = tid >> 6;               // 0..3 (3 = idle)
        float2 rt[3][3];
        #pragma unroll
        for (int r = 0; r < 3; r++)
            #pragma unroll
            for (int bj = 0; bj < 3; bj++) rt[r][bj] = make_float2(0.f, 0.f);

        if (band < 3) {
            const uint32_t* base = sHH + (band * 27) * SHH_STR + cp;
            #pragma unroll
            for (int j = 0; j < 9; j++) {
                float2 v0 = h2f2(base[j * SHH_STR]);
                float2 v1 = h2f2(base[(9 + j) * SHH_STR]);
                float2 v2 = h2f2(base[(18 + j) * SHH_STR]);
                sCT[(band * 9 + j) * 64 + cp] =
                    make_float2(v0.x + v1.x + v2.x, v0.y + v1.y + v2.y);
                int bj = j / 3;
                rt[0][bj].x += v0.x; rt[0][bj].y += v0.y;
                rt[1][bj].x += v1.x; rt[1][bj].y += v1.y;
                rt[2][bj].x += v2.x; rt[2][bj].y += v2.y;
            }
        }
        __syncthreads();
        if (band < 3) {
            float2 RS[3], BX[3];
            #pragma unroll
            for (int r = 0; r < 3; r++)
                RS[r] = make_float2(rt[r][0].x + rt[r][1].x + rt[r][2].x,
                                    rt[r][0].y + rt[r][1].y + rt[r][2].y);
            #pragma unroll
            for (int bj = 0; bj < 3; bj++)
                BX[bj] = make_float2(rt[0][bj].x + rt[1][bj].x + rt[2][bj].x,
                                     rt[0][bj].y + rt[1][bj].y + rt[2][bj].y);
            const float biasX = sB[128 + 2 * cp];
            const float biasY = sB[128 + 2 * cp + 1];
            float accX = 0.0f, accY = 0.0f;
            #pragma unroll
            for (int j = 0; j < 9; j++) {
                float2 c0 = sCT[j * 64 + cp];
                float2 c1 = sCT[(9 + j) * 64 + cp];
                float2 c2 = sCT[(18 + j) * 64 + cp];
                float CjX = c0.x + c1.x + c2.x;
                float CjY = c0.y + c1.y + c2.y;
                float coX = (band == 0) ? c0.x : ((band == 1) ? c1.x : c2.x);
                float coY = (band == 0) ? c0.y : ((band == 1) ? c1.y : c2.y);
                int bj = j / 3;
                #pragma unroll
                for (int r = 0; r < 3; r++) {
                    float uX = RS[r].x + BX[bj].x - rt[r][bj].x + CjX - coX;
                    float uY = RS[r].y + BX[bj].y - rt[r][bj].y + CjY - coY;
                    float vX = uX * (1.0f / 21.0f) + biasX;
                    float vY = uY * (1.0f / 21.0f) + biasY;
                    accX += vX > 0.0f ? vX : 0.0f;
                    accY += vY > 0.0f ? vY : 0.0f;
                }
            }
            sPoolP[band * 64 + cp] = make_float2(accX, accY);
        }
    }
    __syncthreads();
    if (tid < 64) {
        float2 p0 = sPoolP[tid], p1 = sPoolP[64 + tid], p2 = sPoolP[128 + tid];
        ((float2*)sP)[tid] = make_float2(
            (p0.x + p1.x + p2.x) * (1.0f / 81.0f),
            (p0.y + p1.y + p2.y) * (1.0f / 81.0f));
    }
    __syncthreads();

    // ---- Phase 5: heads, k-split across 208 threads ----
    {
        int half = (tid >= 128) ? 1 : 0;
        int idx  = half ? tid - 128 : tid;
        if (idx < 104) {
            const float* W; const float* bb; int nc, col;
            if (idx < 4)       { W = Wa; bb = ba; nc = 4;  col = idx; }
            else if (idx < 85) { W = Wc; bb = bc; nc = 81; col = idx - 4; }
            else if (idx < 94) { W = Wn; bb = bn; nc = 9;  col = idx - 85; }
            else               { W = Wt; bb = bt; nc = 10; col = idx - 94; }
            float acc = half ? 0.0f : bb[col];
            int kb = half << 6;
            #pragma unroll 16
            for (int k = 0; k < 64; k++)
                acc = fmaf(sP[kb + k], W[(kb + k) * nc + col], acc);
            sHeadP[half * 104 + idx] = acc;
        }
    }
    __syncthreads();
    if (tid < 104) {
        int col; size_t off;
        if (tid < 4)       { col = tid;      off = (size_t)g * 4 + col; }
        else if (tid < 85) { col = tid - 4;  off = 8192u   + (size_t)g * 81 + col; }
        else if (tid < 94) { col = tid - 85; off = 174080u + (size_t)g * 9  + col; }
        else               { col = tid - 94; off = 192512u + (size_t)g * 10 + col; }
        out[off] = sHeadP[tid] + sHeadP[104 + tid];
    }
}

extern "C" void kernel_launch(void* const* d_in, const int* in_sizes, int n_in,
                              void* d_out, int out_size)
{
    const float* x  = (const float*)d_in[0];
    const float* W1 = (const float*)d_in[3];
    const float* b1 = (const float*)d_in[4];
    const float* W2 = (const float*)d_in[5];
    const float* b2 = (const float*)d_in[6];
    const float* Wa = (const float*)d_in[7];
    const float* ba = (const float*)d_in[8];
    const float* Wc = (const float*)d_in[9];
    const float* bc = (const float*)d_in[10];
    const float* Wn = (const float*)d_in[11];
    const float* bn = (const float*)d_in[12];
    const float* Wt = (const float*)d_in[13];
    const float* bt = (const float*)d_in[14];
    float* out = (float*)d_out;

    const int nGraphs = in_sizes[0] / (NCELL * 10);   // 2048
    const size_t smemBytes = (size_t)SM_FLOATS * sizeof(float);  // ~61 KB

    prep_w2_kernel<<<16, 256>>>(W2);

    cudaFuncSetAttribute(sudoku_gnn_kernel,
                         cudaFuncAttributeMaxDynamicSharedMemorySize,
                         (int)smemBytes);
    sudoku_gnn_kernel<<<nGraphs, TPB, smemBytes>>>(
        x, W1, b1, b2, Wa, ba, Wc, bc, Wn, bn, Wt, bt, out);
}

// round 17
// speedup vs baseline: 1.5253x; 1.2043x over previous
#include <cuda_runtime.h>
#include <cuda_fp16.h>
#include <stdint.h>

#define NCELL 81
#define TPB   256

// fp16 A tile: row stride 136 halves (272 B), 16B-aligned, ldmatrix conflict-free
#define ASTR  136
// ---- float-index smem layout (15332 floats = 61328 B) ----
#define AHI_F 0        // A fp16 96 x 136 halves (6528 f)
#define SHH_F 6528     // Y2 half2 81 x 68 words (5508 f)
#define SHH_STR 68
#define SW1_F 12036    // W1 10x128 (1280)
#define SX_F  13316    // x 81x10 (816)
#define SZ_F  14132    // A_hat@x 81x10 (816)
#define SP_F  14948    // pooled (128)
#define SB_F  15076    // b1|b2 (256)
#define SM_FLOATS 15332
// scratch overlapping the (temporally dead) A region:
#define TRIP_F  0      // phase 1 trips (540 f)
#define CT_F    0      // phase 4 coltrip half2 [band*9+j][cp]: 27*64 = 1728 f
#define POOLP_F 1728   // pool partials float2: 3*64*2 = 384 f
#define HEADP_F 2112   // head partials 208 f

// ---- prepacked W2 (single fp16) in device-global, B-fragment quad order ----
// layout: [n][g][q][4] halves, quad q holds k = 16g + {2q, 2q+1, 2q+8, 2q+9}
__device__ __align__(16) uint16_t gBhi[128 * 128];

__global__ void prep_w2_kernel(const float* __restrict__ W2) {
    int idx = blockIdx.x * blockDim.x + threadIdx.x;   // 4096 quads
    if (idx >= 4096) return;
    int n = idx >> 5, g = (idx >> 2) & 7, q = idx & 3;
    int kb = 16 * g + 2 * q;
    int ks[4] = { kb, kb + 1, kb + 8, kb + 9 };
    uint16_t h[4];
    #pragma unroll
    for (int e = 0; e < 4; e++)
        h[e] = __half_as_ushort(__float2half_rn(W2[ks[e] * 128 + n]));
    uint64_t hv;
    memcpy(&hv, h, 8);
    *(uint64_t*)(gBhi + n * 128 + g * 16 + q * 4) = hv;
}

// ================= constexpr index tables (phase 1) =========================
struct U54 { unsigned v[54]; };
struct U81 { unsigned v[81]; };

static constexpr U54 mkA() {
    U54 r{};
    for (int t = 0; t < 54; t++) {
        int c0 = 0, c1 = 0, c2 = 0;
        if (t < 27) { int i = t / 3, bj = t % 3, base = i * 9 + bj * 3;
                      c0 = base; c1 = base + 1; c2 = base + 2; }
        else        { int u = t - 27, j = u / 3, bi = u % 3, base = bi * 27 + j;
                      c0 = base; c1 = base + 9; c2 = base + 18; }
        r.v[t] = (unsigned)(c0 | (c1 << 8) | (c2 << 16));
    }
    return r;
}
static constexpr U81 mkD() {
    U81 r{};
    for (int cell = 0; cell < 81; cell++) {
        int i = cell / 9, j = cell % 9, bi = i / 3, bj = j / 3;
        r.v[cell] = (unsigned)(i | (j << 4) | (bi << 8) | (bj << 12));
    }
    return r;
}
__constant__ U54 cTabA = mkA();
__constant__ U81 cTabD = mkD();

// ================= PTX helpers ==============================================
__device__ __forceinline__ uint32_t smem_to_u32(const void* p) {
    uint32_t a;
    asm("{ .reg .u64 t; cvta.to.shared.u64 t, %1; cvt.u32.u64 %0, t; }"
        : "=r"(a) : "l"(p));
    return a;
}
__device__ __forceinline__ uint32_t cvt2f16(float v0, float v1) {
    uint32_t r;
    asm("cvt.rn.f16x2.f32 %0, %1, %2;" : "=r"(r) : "f"(v1), "f"(v0));
    return r;
}
__device__ __forceinline__ float2 h2f2(uint32_t u) {
    __half2 h = *(__half2*)&u;
    return __half22float2(h);
}
__device__ __forceinline__ void ldsm4(uint32_t& r0, uint32_t& r1,
                                      uint32_t& r2, uint32_t& r3, uint32_t addr) {
    asm volatile("ldmatrix.sync.aligned.m8n8.x4.shared.b16 {%0,%1,%2,%3}, [%4];"
                 : "=r"(r0), "=r"(r1), "=r"(r2), "=r"(r3) : "r"(addr));
}
__device__ __forceinline__ void mma16816(float* c, uint32_t a0, uint32_t a1,
                                         uint32_t a2, uint32_t a3,
                                         uint32_t b0, uint32_t b1) {
    asm volatile(
        "mma.sync.aligned.m16n8k16.row.col.f32.f16.f16.f32 "
        "{%0,%1,%2,%3}, {%4,%5,%6,%7}, {%8,%9}, {%0,%1,%2,%3};"
        : "+f"(c[0]), "+f"(c[1]), "+f"(c[2]), "+f"(c[3])
        : "r"(a0), "r"(a1), "r"(a2), "r"(a3), "r"(b0), "r"(b1));
}

// ================= main kernel ==============================================
__global__ __launch_bounds__(TPB, 2)
void sudoku_gnn_kernel(const float* __restrict__ x,
                       const float* __restrict__ W1, const float* __restrict__ b1,
                       const float* __restrict__ b2,
                       const float* __restrict__ Wa, const float* __restrict__ ba,
                       const float* __restrict__ Wc, const float* __restrict__ bc,
                       const float* __restrict__ Wn, const float* __restrict__ bn,
                       const float* __restrict__ Wt, const float* __restrict__ bt,
                       float* __restrict__ out)
{
    extern __shared__ float sm[];
    char*     smb = (char*)sm;
    uint32_t* sHH = (uint32_t*)(sm + SHH_F);
    float*    sW1 = sm + SW1_F;
    float*    sX  = sm + SX_F;
    float*    sZ  = sm + SZ_F;
    float*    sP  = sm + SP_F;
    float*    sB  = sm + SB_F;
    float*    sTripF = sm + TRIP_F;
    uint32_t* sCT   = (uint32_t*)(sm + CT_F);
    float2*   sPoolP = (float2*)(sm + POOLP_F);
    float*    sHeadP = sm + HEADP_F;

    const int tid  = threadIdx.x;
    const int wid  = tid >> 5;
    const int lane = tid & 31;
    const int g    = blockIdx.x;
    const uint32_t smu = smem_to_u32(sm);

    // ---- stage: W1 (grid-stride, 320 float4), x, biases ----
    for (int i = tid; i < 320; i += TPB)
        ((float4*)sW1)[i] = ((const float4*)W1)[i];
    {
        const float* xg = x + (size_t)g * (NCELL * 10);
        for (int i = tid; i < NCELL * 10; i += TPB) sX[i] = xg[i];
    }
    if (tid < 128) { sB[tid] = b1[tid]; sB[128 + tid] = b2[tid]; }
    __syncthreads();

    // ---- Phase 1a: triples on 10 raw channels ----
    for (int it = tid; it < 54 * 10; it += TPB) {
        int t = it / 10, f = it - t * 10;
        unsigned pk = cTabA.v[t];
        sTripF[it] = sX[(pk & 255) * 10 + f] + sX[((pk >> 8) & 255) * 10 + f]
                   + sX[((pk >> 16) & 255) * 10 + f];
    }
    __syncthreads();
    // ---- Phase 1b: Zx = union/21 directly from trips ----
    for (int it = tid; it < NCELL * 10; it += TPB) {
        int cell = it / 10, f = it - cell * 10;
        unsigned pk = cTabD.v[cell];
        int i  = pk & 15, j = (pk >> 4) & 15;
        int bi = (pk >> 8) & 3, bj = (pk >> 12) & 3;
        const float* T = sTripF;
        float r0 = T[(i * 3 + 0) * 10 + f];
        float r1 = T[(i * 3 + 1) * 10 + f];
        float r2 = T[(i * 3 + 2) * 10 + f];
        float c0 = T[(27 + j * 3 + 0) * 10 + f];
        float c1 = T[(27 + j * 3 + 1) * 10 + f];
        float c2 = T[(27 + j * 3 + 2) * 10 + f];
        float x0 = T[((3 * bi + 0) * 3 + bj) * 10 + f];
        float x1 = T[((3 * bi + 1) * 3 + bj) * 10 + f];
        float x2 = T[((3 * bi + 2) * 3 + bj) * 10 + f];
        float rtrip = (bj == 0) ? r0 : ((bj == 1) ? r1 : r2);
        float ctrip = (bi == 0) ? c0 : ((bi == 1) ? c1 : c2);
        float agg = (r0 + r1 + r2) + (c0 + c1 + c2) + (x0 + x1 + x2)
                  - rtrip - ctrip;
        sZ[it] = agg * (1.0f / 21.0f);
    }
    __syncthreads();

    // ---- Phase 2: H1 = relu(Zx@W1 + b1) -> fp16 into A tile ----
    {
        const int kp  = tid & 63;           // k-pair, k = 2*kp
        const int grp = tid >> 6;           // 0..3, 24 cells each
        const int k   = kp << 1;
        float2 w[10];
        #pragma unroll
        for (int f = 0; f < 10; f++) w[f] = *(const float2*)(sW1 + f * 128 + k);
        const float b0 = sB[k], b1v = sB[k + 1];

        int cBeg = grp * 24;
        #pragma unroll 4
        for (int cell = cBeg; cell < cBeg + 24; cell++) {
            uint32_t h = 0u;
            if (cell < NCELL) {
                const float* z = sZ + cell * 10;
                float v0 = b0, v1 = b1v;
                #pragma unroll
                for (int f = 0; f < 10; f++) {
                    float zf = z[f];
                    v0 = fmaf(zf, w[f].x, v0);
                    v1 = fmaf(zf, w[f].y, v1);
                }
                v0 = v0 > 0.0f ? v0 : 0.0f;
                v1 = v1 > 0.0f ? v1 : 0.0f;
                h = cvt2f16(v0, v1);
            }
            uint32_t off = (uint32_t)cell * (ASTR * 2) + (uint32_t)k * 2;
            *(uint32_t*)(smb + AHI_F * 4 + off) = h;
        }
    }
    __syncthreads();

    // ---- Phase 3: Y2 = H1 @ W2 via mma.sync fp16, single term ----
    {
        const int ntb  = (wid & 3) * 4;          // 4 n-tiles (8 ch each)
        const int mtb  = (wid >> 2) * 3;         // 3 m-tiles (16 rows each)
        const int arow = lane & 15;
        const int akoff = (lane & 16) ? 8 : 0;
        const int q4   = (lane & 3) * 4;
        const int nrow = lane >> 2;

        float acc[3][4][4];
        #pragma unroll
        for (int mt = 0; mt < 3; mt++)
            #pragma unroll
            for (int nt = 0; nt < 4; nt++)
                #pragma unroll
                for (int qq = 0; qq < 4; qq++) acc[mt][nt][qq] = 0.0f;

        const uint32_t aHi = smu + AHI_F * 4;
        const uint16_t* bhB = gBhi + q4;

        #pragma unroll
        for (int ks = 0; ks < 8; ks++) {
            const int k0 = ks << 4;
            uint2 bh[4];
            #pragma unroll
            for (int nt = 0; nt < 4; nt++) {
                int n = (ntb + nt) * 8 + nrow;
                bh[nt] = *(const uint2*)(bhB + n * 128 + k0);
            }
            #pragma unroll
            for (int mt = 0; mt < 3; mt++) {
                uint32_t aOff = (uint32_t)((mtb + mt) * 16 + arow) * (ASTR * 2)
                              + (uint32_t)(k0 + akoff) * 2;
                uint32_t ah0, ah1, ah2, ah3;
                ldsm4(ah0, ah1, ah2, ah3, aHi + aOff);
                #pragma unroll
                for (int nt = 0; nt < 4; nt++)
                    mma16816(acc[mt][nt], ah0, ah1, ah2, ah3, bh[nt].x, bh[nt].y);
            }
        }
        // epilogue: pack channel pairs to half2, store into sHH (stride 68)
        const int rbase = lane >> 2;
        const int cpq   = lane & 3;              // colPair within n-tile
        #pragma unroll
        for (int mt = 0; mt < 3; mt++) {
            int row = (mtb + mt) * 16 + rbase;
            #pragma unroll
            for (int nt = 0; nt < 4; nt++) {
                int cp = (ntb + nt) * 4 + cpq;   // channel pair index 0..63
                if (row < NCELL)
                    sHH[row * SHH_STR + cp] = cvt2f16(acc[mt][nt][0], acc[mt][nt][1]);
                if (row + 8 < NCELL)
                    sHH[(row + 8) * SHH_STR + cp] = cvt2f16(acc[mt][nt][2], acc[mt][nt][3]);
            }
        }
    }
    __syncthreads();

    // ---- Phase 4: fused band agg + bias + relu + pool.
    //      Rowtrips live in registers; coltrips via smem as half2. ----
    {
        const int cp   = tid & 63;
        const int band = tid >> 6;               // 0..3 (3 = idle)
        float2 rt[3][3];
        #pragma unroll
        for (int r = 0; r < 3; r++)
            #pragma unroll
            for (int bj = 0; bj < 3; bj++) rt[r][bj] = make_float2(0.f, 0.f);

        if (band < 3) {
            const uint32_t* base = sHH + (band * 27) * SHH_STR + cp;
            #pragma unroll
            for (int j = 0; j < 9; j++) {
                float2 v0 = h2f2(base[j * SHH_STR]);
                float2 v1 = h2f2(base[(9 + j) * SHH_STR]);
                float2 v2 = h2f2(base[(18 + j) * SHH_STR]);
                sCT[(band * 9 + j) * 64 + cp] =
                    cvt2f16(v0.x + v1.x + v2.x, v0.y + v1.y + v2.y);
                int bj = j / 3;
                rt[0][bj].x += v0.x; rt[0][bj].y += v0.y;
                rt[1][bj].x += v1.x; rt[1][bj].y += v1.y;
                rt[2][bj].x += v2.x; rt[2][bj].y += v2.y;
            }
        }
        __syncthreads();
        if (band < 3) {
            float2 RS[3], BX[3];
            #pragma unroll
            for (int r = 0; r < 3; r++)
                RS[r] = make_float2(rt[r][0].x + rt[r][1].x + rt[r][2].x,
                                    rt[r][0].y + rt[r][1].y + rt[r][2].y);
            #pragma unroll
            for (int bj = 0; bj < 3; bj++)
                BX[bj] = make_float2(rt[0][bj].x + rt[1][bj].x + rt[2][bj].x,
                                     rt[0][bj].y + rt[1][bj].y + rt[2][bj].y);
            const float biasX = sB[128 + 2 * cp];
            const float biasY = sB[128 + 2 * cp + 1];
            float accX = 0.0f, accY = 0.0f;
            #pragma unroll
            for (int j = 0; j < 9; j++) {
                float2 c0 = h2f2(sCT[j * 64 + cp]);
                float2 c1 = h2f2(sCT[(9 + j) * 64 + cp]);
                float2 c2 = h2f2(sCT[(18 + j) * 64 + cp]);
                float CjX = c0.x + c1.x + c2.x;
                float CjY = c0.y + c1.y + c2.y;
                float coX = (band == 0) ? c0.x : ((band == 1) ? c1.x : c2.x);
                float coY = (band == 0) ? c0.y : ((band == 1) ? c1.y : c2.y);
                int bj = j / 3;
                #pragma unroll
                for (int r = 0; r < 3; r++) {
                    float uX = RS[r].x + BX[bj].x - rt[r][bj].x + CjX - coX;
                    float uY = RS[r].y + BX[bj].y - rt[r][bj].y + CjY - coY;
                    float vX = uX * (1.0f / 21.0f) + biasX;
                    float vY = uY * (1.0f / 21.0f) + biasY;
                    accX += vX > 0.0f ? vX : 0.0f;
                    accY += vY > 0.0f ? vY : 0.0f;
                }
            }
            sPoolP[band * 64 + cp] = make_float2(accX, accY);
        }
    }
    __syncthreads();
    if (tid < 64) {
        float2 p0 = sPoolP[tid], p1 = sPoolP[64 + tid], p2 = sPoolP[128 + tid];
        ((float2*)sP)[tid] = make_float2(
            (p0.x + p1.x + p2.x) * (1.0f / 81.0f),
            (p0.y + p1.y + p2.y) * (1.0f / 81.0f));
    }
    __syncthreads();

    // ---- Phase 5: heads, k-split across 208 threads ----
    {
        int half = (tid >= 128) ? 1 : 0;
        int idx  = half ? tid - 128 : tid;
        if (idx < 104) {
            const float* W; const float* bb; int nc, col;
            if (idx < 4)       { W = Wa; bb = ba; nc = 4;  col = idx; }
            else if (idx < 85) { W = Wc; bb = bc; nc = 81; col = idx - 4; }
            else if (idx < 94) { W = Wn; bb = bn; nc = 9;  col = idx - 85; }
            else               { W = Wt; bb = bt; nc = 10; col = idx - 94; }
            float acc = half ? 0.0f : bb[col];
            int kb = half << 6;
            #pragma unroll 16
            for (int k = 0; k < 64; k++)
                acc = fmaf(sP[kb + k], W[(kb + k) * nc + col], acc);
            sHeadP[half * 104 + idx] = acc;
        }
    }
    __syncthreads();
    if (tid < 104) {
        int col; size_t off;
        if (tid < 4)       { col = tid;      off = (size_t)g * 4 + col; }
        else if (tid < 85) { col = tid - 4;  off = 8192u   + (size_t)g * 81 + col; }
        else if (tid < 94) { col = tid - 85; off = 174080u + (size_t)g * 9  + col; }
        else               { col = tid - 94; off = 192512u + (size_t)g * 10 + col; }
        out[off] = sHeadP[tid] + sHeadP[104 + tid];
    }
}

extern "C" void kernel_launch(void* const* d_in, const int* in_sizes, int n_in,
                              void* d_out, int out_size)
{
    const float* x  = (const float*)d_in[0];
    const float* W1 = (const float*)d_in[3];
    const float* b1 = (const float*)d_in[4];
    const float* W2 = (const float*)d_in[5];
    const float* b2 = (const float*)d_in[6];
    const float* Wa = (const float*)d_in[7];
    const float* ba = (const float*)d_in[8];
    const float* Wc = (const float*)d_in[9];
    const float* bc = (const float*)d_in[10];
    const float* Wn = (const float*)d_in[11];
    const float* bn = (const float*)d_in[12];
    const float* Wt = (const float*)d_in[13];
    const float* bt = (const float*)d_in[14];
    float* out = (float*)d_out;

    const int nGraphs = in_sizes[0] / (NCELL * 10);   // 2048
    const size_t smemBytes = (size_t)SM_FLOATS * sizeof(float);  // ~61 KB

    prep_w2_kernel<<<16, 256>>>(W2);

    cudaFuncSetAttribute(sudoku_gnn_kernel,
                         cudaFuncAttributeMaxDynamicSharedMemorySize,
                         (int)smemBytes);
    sudoku_gnn_kernel<<<nGraphs, TPB, smemBytes>>>(
        x, W1, b1, b2, Wa, ba, Wc, bc, Wn, bn, Wt, bt, out);
}